// round 1
// baseline (speedup 1.0000x reference)
#include <cuda_runtime.h>
#include <math.h>

// Problem constants
#define BATCH    1024
#define TSTEPS   80
#define DIM      512
#define CLS      78          // VOCAB+1
#define BLANK    77
#define PRED_LEN 30
#define ROWS     (BATCH * TSTEPS)   // 81920
#define PAIRS    (ROWS / 2)         // 40960

#define THREADS  512
#define WARPS    (THREADS / 32)

// argmax path scratch (device global: no allocations allowed)
__device__ int g_best[ROWS];

// ---------------------------------------------------------------------------
// Kernel 1: fused GEMM + bias + softmax + argmax
//  - W^T cached in shared memory once per (persistent) block
//  - each warp handles 2 rows per iteration (W smem bytes amortized over 2 rows)
// ---------------------------------------------------------------------------
__global__ void __launch_bounds__(THREADS, 1)
gemm_softmax_argmax_kernel(const float* __restrict__ feat,
                           const float* __restrict__ Wg,
                           const float* __restrict__ bg,
                           float* __restrict__ out)
{
    extern __shared__ float smem[];
    float* Wt     = smem;                       // [CLS][DIM], Wt[c*DIM + k]
    float* bs     = Wt + CLS * DIM;             // [CLS]
    float* scores = bs + CLS;                   // [WARPS][2][CLS]

    const int tid = threadIdx.x;

    // Load W transposed into smem (gmem reads coalesced; smem writes scattered ok)
    for (int idx = tid; idx < CLS * DIM; idx += THREADS) {
        int k = idx / CLS;
        int c = idx - k * CLS;
        Wt[c * DIM + k] = Wg[idx];
    }
    if (tid < CLS) bs[tid] = bg[tid];
    __syncthreads();

    const int lane = tid & 31;
    const int warp = tid >> 5;
    float* my_scores = scores + warp * 2 * CLS;

    const int gw = blockIdx.x * WARPS + warp;
    const int nw = gridDim.x * WARPS;
    const float4* Wt4 = (const float4*)Wt;

    for (int p = gw; p < PAIRS; p += nw) {
        const int r0 = 2 * p;
        const int r1 = r0 + 1;

        // Load both feature rows into registers (coalesced float4)
        const float4* f0p = (const float4*)(feat + (size_t)r0 * DIM);
        const float4* f1p = (const float4*)(feat + (size_t)r1 * DIM);
        float4 f0[4], f1[4];
        #pragma unroll
        for (int j = 0; j < 4; j++) {
            f0[j] = f0p[lane + 32 * j];
            f1[j] = f1p[lane + 32 * j];
        }

        // 78 dot products of length 512, two rows per pass
        for (int c = 0; c < CLS; c++) {
            float a0 = 0.f, a1 = 0.f;
            #pragma unroll
            for (int j = 0; j < 4; j++) {
                float4 w = Wt4[c * (DIM / 4) + lane + 32 * j];
                a0 = fmaf(f0[j].x, w.x, a0); a0 = fmaf(f0[j].y, w.y, a0);
                a0 = fmaf(f0[j].z, w.z, a0); a0 = fmaf(f0[j].w, w.w, a0);
                a1 = fmaf(f1[j].x, w.x, a1); a1 = fmaf(f1[j].y, w.y, a1);
                a1 = fmaf(f1[j].z, w.z, a1); a1 = fmaf(f1[j].w, w.w, a1);
            }
            #pragma unroll
            for (int s = 16; s; s >>= 1) {
                a0 += __shfl_xor_sync(0xffffffffu, a0, s);
                a1 += __shfl_xor_sync(0xffffffffu, a1, s);
            }
            if (lane == 0) {
                my_scores[c]       = a0 + bs[c];
                my_scores[CLS + c] = a1 + bs[c];
            }
        }
        __syncwarp();

        // Softmax + argmax per row (lane covers classes lane, lane+32, lane+64)
        #pragma unroll
        for (int j = 0; j < 2; j++) {
            const int row = j ? r1 : r0;
            const float* s = my_scores + j * CLS;

            const float v0 = s[lane];                                        // lane < 78 always
            const float v1 = (lane + 32 < CLS) ? s[lane + 32] : -INFINITY;
            const float v2 = (lane + 64 < CLS) ? s[lane + 64] : -INFINITY;

            float m = fmaxf(v0, fmaxf(v1, v2));
            #pragma unroll
            for (int st = 16; st; st >>= 1)
                m = fmaxf(m, __shfl_xor_sync(0xffffffffu, m, st));

            const float e0 = __expf(v0 - m);
            const float e1 = (lane + 32 < CLS) ? __expf(v1 - m) : 0.f;
            const float e2 = (lane + 64 < CLS) ? __expf(v2 - m) : 0.f;

            float sum = e0 + e1 + e2;
            #pragma unroll
            for (int st = 16; st; st >>= 1)
                sum += __shfl_xor_sync(0xffffffffu, sum, st);
            const float inv = 1.0f / sum;

            float* o = out + (size_t)row * CLS;
            o[lane] = e0 * inv;
            if (lane + 32 < CLS) o[lane + 32] = e1 * inv;
            if (lane + 64 < CLS) o[lane + 64] = e2 * inv;

            // argmax with first-index tie-break (ascending order + strict > keeps first)
            float bv = v0; int bi = lane;
            if (v1 > bv) { bv = v1; bi = lane + 32; }
            if (v2 > bv) { bv = v2; bi = lane + 64; }
            #pragma unroll
            for (int st = 16; st; st >>= 1) {
                float ov = __shfl_xor_sync(0xffffffffu, bv, st);
                int   oi = __shfl_xor_sync(0xffffffffu, bi, st);
                if (ov > bv || (ov == bv && oi < bi)) { bv = ov; bi = oi; }
            }
            if (lane == 0) g_best[row] = bi;
        }
    }
}

// ---------------------------------------------------------------------------
// Kernel 2: CTC greedy collapse (merge repeats, drop blanks, pad -1 to 30)
// ---------------------------------------------------------------------------
__global__ void ctc_decode_kernel(float* __restrict__ out)
{
    const int b = blockIdx.x * blockDim.x + threadIdx.x;
    if (b >= BATCH) return;

    float res[PRED_LEN];
    #pragma unroll
    for (int i = 0; i < PRED_LEN; i++) res[i] = -1.0f;

    const int* bp = g_best + b * TSTEPS;
    int prev = -1;
    int n = 0;
    for (int t = 0; t < TSTEPS; t++) {
        const int v = bp[t];
        if (v != BLANK && v != prev && n < PRED_LEN) res[n++] = (float)v;
        prev = v;
    }

    float* o = out + (size_t)ROWS * CLS + (size_t)b * PRED_LEN;
    #pragma unroll
    for (int i = 0; i < PRED_LEN; i++) o[i] = res[i];
}

// ---------------------------------------------------------------------------
extern "C" void kernel_launch(void* const* d_in, const int* in_sizes, int n_in,
                              void* d_out, int out_size)
{
    const float* feat = (const float*)d_in[0];   // [1024, 80, 512] f32
    const float* W    = (const float*)d_in[1];   // [512, 78] f32
    const float* b    = (const float*)d_in[2];   // [78] f32
    float* out        = (float*)d_out;

    const int smem_bytes = (CLS * DIM + CLS + WARPS * 2 * CLS) * (int)sizeof(float);
    cudaFuncSetAttribute(gemm_softmax_argmax_kernel,
                         cudaFuncAttributeMaxDynamicSharedMemorySize, smem_bytes);

    gemm_softmax_argmax_kernel<<<148, THREADS, smem_bytes>>>(feat, W, b, out);

    // Decoded labels follow the logits in d_out (if the harness expects them)
    if (out_size >= ROWS * CLS + BATCH * PRED_LEN) {
        ctc_decode_kernel<<<(BATCH + 255) / 256, 256>>>(out);
    }
}

// round 3
// speedup vs baseline: 3.2076x; 3.2076x over previous
#include <cuda_runtime.h>
#include <cuda_bf16.h>
#include <cstdint>
#include <math.h>

// ---------------- problem constants ----------------
#define BATCH    1024
#define TSTEPS   80
#define DIM      512
#define CLS      78
#define BLANK    77
#define PRED_LEN 30
#define ROWS     (BATCH * TSTEPS)     // 81920

#define TILE_M   128
#define NTILES   (ROWS / TILE_M)      // 640
#define NCTAS    148
#define THREADS  256                  // 8 warps, 16 rows each
#define NKC      16                   // k32 chunks per tile (512/32)

// ---------------- smem layout (bytes) ----------------
// B rows: n in [0,80), row stride 1088 (1024 data + 64 pad -> conflict-free LDS.128)
#define B_STRIDE  1088
#define B_BYTES   (80 * B_STRIDE)     // 87040 per (hi|lo)
// A rows: 128 rows, stride 192: [hi 64B][lo 64B][pad 64B]
#define A_STRIDE  192
#define A_BYTES   (TILE_M * A_STRIDE) // 24576 per buffer
#define SM_BHI    0
#define SM_BLO    B_BYTES
#define SM_A0     (2 * B_BYTES)                // 174080
#define SM_A1     (SM_A0 + A_BYTES)
#define SM_TOTAL  (SM_A1 + A_BYTES)            // 223232

__device__ uint16_t g_Whi[80 * 544];
__device__ uint16_t g_Wlo[80 * 544];
__device__ int g_best[ROWS];

// k-permutation: within each k32 group (64B), element k sits so that a thread's
// mma fragment b32s {(2t,2t+1),(2t+8,2t+9)} x {k16 step0, step1} are one 16B slot.
__device__ __forceinline__ int kperm(int k) {
    int grp = k >> 5, r = k & 31;
    int s = r >> 4;              // k16 step within k32
    int j = r & 15;
    int t = (j & 7) >> 1;        // thread-in-group
    int idx = (k & 1) | ((j >> 3) << 1);
    return grp * 32 + t * 8 + s * 4 + idx;   // u16 index within row
}

__device__ __forceinline__ uint32_t pack_bf16(float a, float b) {
    __nv_bfloat16 ha = __float2bfloat16_rn(a);
    __nv_bfloat16 hb = __float2bfloat16_rn(b);
    return (uint32_t)__bfloat16_as_ushort(ha) |
           ((uint32_t)__bfloat16_as_ushort(hb) << 16);
}

__device__ __forceinline__ void mma16816(float* c, uint32_t a0, uint32_t a1,
                                         uint32_t a2, uint32_t a3,
                                         uint32_t b0, uint32_t b1) {
    asm volatile(
        "mma.sync.aligned.m16n8k16.row.col.f32.bf16.bf16.f32 "
        "{%0,%1,%2,%3}, {%4,%5,%6,%7}, {%8,%9}, {%0,%1,%2,%3};"
        : "+f"(c[0]), "+f"(c[1]), "+f"(c[2]), "+f"(c[3])
        : "r"(a0), "r"(a1), "r"(a2), "r"(a3), "r"(b0), "r"(b1));
}

// ---------------------------------------------------------------------------
// Prep: split W (512x78 fp32) into bf16 hi/lo, permuted+padded layout [80][544]
// ---------------------------------------------------------------------------
__global__ void prep_w_kernel(const float* __restrict__ W)
{
    int idx = blockIdx.x * blockDim.x + threadIdx.x;
    if (idx >= 80 * 512) return;
    int n = idx >> 9, k = idx & 511;
    float v = (n < CLS) ? W[k * CLS + n] : 0.0f;
    __nv_bfloat16 h = __float2bfloat16_rn(v);
    __nv_bfloat16 l = __float2bfloat16_rn(v - __bfloat162float(h));
    int p = n * 544 + kperm(k);
    g_Whi[p] = __bfloat16_as_ushort(h);
    g_Wlo[p] = __bfloat16_as_ushort(l);
}

// ---------------------------------------------------------------------------
// Main: bf16-split HMMA GEMM + bias + softmax + argmax (persistent CTAs)
// ---------------------------------------------------------------------------
__global__ void __launch_bounds__(THREADS, 1)
gemm_softmax_kernel(const float* __restrict__ feat,
                    const float* __restrict__ bg,
                    float* __restrict__ out)
{
    extern __shared__ char sm[];
    const int tid  = threadIdx.x;
    const int lane = tid & 31;
    const int warp = tid >> 5;
    const int g    = lane >> 2;     // groupID (row within 8)
    const int t    = lane & 3;      // thread-in-group (k / col pairs)

    // ---- copy resident B (hi+lo) from gmem (L2) to smem ----
    {
        const uint4* sh = (const uint4*)g_Whi;
        const uint4* sl = (const uint4*)g_Wlo;
        uint4* dh = (uint4*)(sm + SM_BHI);
        uint4* dl = (uint4*)(sm + SM_BLO);
        for (int i = tid; i < B_BYTES / 16; i += THREADS) { dh[i] = sh[i]; dl[i] = sl[i]; }
    }

    // ---- per-thread bias pairs for cols 8j+2t, 8j+2t+1 ----
    float bb[10][2];
    #pragma unroll
    for (int j = 0; j < 10; j++) {
        int col = 8 * j + 2 * t;
        bb[j][0] = (col     < CLS) ? bg[col]     : 0.0f;
        bb[j][1] = (col + 1 < CLS) ? bg[col + 1] : 0.0f;
    }
    __syncthreads();

    const int rowq = tid >> 3;      // A-load row-within-32
    const int q    = tid & 7;       // A-load float4-within-k32
    const int sts_off = ((q >> 2) << 3) + ((q & 1) << 5) + (((q >> 1) & 1) << 2);
    const int wrow = warp * 16;

    for (int tile = blockIdx.x; tile < NTILES; tile += gridDim.x) {
        const size_t tb = (size_t)tile * TILE_M;
        const float4* f4 = (const float4*)feat;

        float c[10][4];
        #pragma unroll
        for (int j = 0; j < 10; j++)
            { c[j][0] = 0.f; c[j][1] = 0.f; c[j][2] = 0.f; c[j][3] = 0.f; }

        float4 f[4];
        // prologue: chunk 0
        #pragma unroll
        for (int p = 0; p < 4; p++)
            f[p] = f4[(tb + p * 32 + rowq) * 128 + q];
        {
            char* ab = sm + SM_A0;
            #pragma unroll
            for (int p = 0; p < 4; p++) {
                char* base = ab + (p * 32 + rowq) * A_STRIDE;
                *(uint32_t*)(base + sts_off)          = pack_bf16(f[p].x, f[p].y);
                *(uint32_t*)(base + sts_off + 16)     = pack_bf16(f[p].z, f[p].w);
                float hx = __bfloat162float(__float2bfloat16_rn(f[p].x));
                float hy = __bfloat162float(__float2bfloat16_rn(f[p].y));
                float hz = __bfloat162float(__float2bfloat16_rn(f[p].z));
                float hw = __bfloat162float(__float2bfloat16_rn(f[p].w));
                *(uint32_t*)(base + 64 + sts_off)     = pack_bf16(f[p].x - hx, f[p].y - hy);
                *(uint32_t*)(base + 64 + sts_off + 16)= pack_bf16(f[p].z - hz, f[p].w - hw);
            }
        }
        __syncthreads();

        for (int kc = 0; kc < NKC; kc++) {
            if (kc < NKC - 1) {
                #pragma unroll
                for (int p = 0; p < 4; p++)
                    f[p] = f4[(tb + p * 32 + rowq) * 128 + (kc + 1) * 8 + q];
            }
            // ---- compute on buffer kc&1 ----
            {
                const char* A = sm + ((kc & 1) ? SM_A1 : SM_A0);
                const char* a0p = A + (wrow + g) * A_STRIDE + t * 16;
                const char* a1p = A + (wrow + g + 8) * A_STRIDE + t * 16;
                uint4 ah0 = *(const uint4*)(a0p);
                uint4 ah1 = *(const uint4*)(a1p);
                uint4 al0 = *(const uint4*)(a0p + 64);
                uint4 al1 = *(const uint4*)(a1p + 64);
                const int boff = kc * 64 + t * 16;
                #pragma unroll
                for (int j = 0; j < 10; j++) {
                    const int n = 8 * j + g;
                    uint4 bh = *(const uint4*)(sm + SM_BHI + n * B_STRIDE + boff);
                    uint4 bl = *(const uint4*)(sm + SM_BLO + n * B_STRIDE + boff);
                    // k16 step 0
                    mma16816(c[j], ah0.x, ah1.x, ah0.y, ah1.y, bh.x, bh.y);
                    mma16816(c[j], ah0.x, ah1.x, ah0.y, ah1.y, bl.x, bl.y);
                    mma16816(c[j], al0.x, al1.x, al0.y, al1.y, bh.x, bh.y);
                    // k16 step 1
                    mma16816(c[j], ah0.z, ah1.z, ah0.w, ah1.w, bh.z, bh.w);
                    mma16816(c[j], ah0.z, ah1.z, ah0.w, ah1.w, bl.z, bl.w);
                    mma16816(c[j], al0.z, al1.z, al0.w, al1.w, bh.z, bh.w);
                }
            }
            __syncthreads();
            if (kc < NKC - 1) {
                char* ab = sm + (((kc + 1) & 1) ? SM_A1 : SM_A0);
                #pragma unroll
                for (int p = 0; p < 4; p++) {
                    char* base = ab + (p * 32 + rowq) * A_STRIDE;
                    *(uint32_t*)(base + sts_off)           = pack_bf16(f[p].x, f[p].y);
                    *(uint32_t*)(base + sts_off + 16)      = pack_bf16(f[p].z, f[p].w);
                    float hx = __bfloat162float(__float2bfloat16_rn(f[p].x));
                    float hy = __bfloat162float(__float2bfloat16_rn(f[p].y));
                    float hz = __bfloat162float(__float2bfloat16_rn(f[p].z));
                    float hw = __bfloat162float(__float2bfloat16_rn(f[p].w));
                    *(uint32_t*)(base + 64 + sts_off)      = pack_bf16(f[p].x - hx, f[p].y - hy);
                    *(uint32_t*)(base + 64 + sts_off + 16) = pack_bf16(f[p].z - hz, f[p].w - hw);
                }
                __syncthreads();
            }
        }

        // ---- epilogue: bias + softmax + argmax; rows r0 = tile*128+wrow+g, r1=+8 ----
        const int row0 = tile * TILE_M + wrow + g;
        const int row1 = row0 + 8;

        float m0 = -INFINITY, m1 = -INFINITY;
        int i0 = 0, i1 = 0;
        #pragma unroll
        for (int j = 0; j < 10; j++) {
            #pragma unroll
            for (int h = 0; h < 2; h++) {
                int col = 8 * j + 2 * t + h;
                if (col < CLS) {
                    float v0 = c[j][h]     + bb[j][h];
                    float v1 = c[j][2 + h] + bb[j][h];
                    c[j][h]     = v0;
                    c[j][2 + h] = v1;
                    if (v0 > m0) { m0 = v0; i0 = col; }
                    if (v1 > m1) { m1 = v1; i1 = col; }
                }
            }
        }
        #pragma unroll
        for (int d = 1; d <= 2; d <<= 1) {
            float om0 = __shfl_xor_sync(0xffffffffu, m0, d);
            int   oi0 = __shfl_xor_sync(0xffffffffu, i0, d);
            if (om0 > m0 || (om0 == m0 && oi0 < i0)) { m0 = om0; i0 = oi0; }
            float om1 = __shfl_xor_sync(0xffffffffu, m1, d);
            int   oi1 = __shfl_xor_sync(0xffffffffu, i1, d);
            if (om1 > m1 || (om1 == m1 && oi1 < i1)) { m1 = om1; i1 = oi1; }
        }
        float s0 = 0.f, s1 = 0.f;
        #pragma unroll
        for (int j = 0; j < 10; j++) {
            #pragma unroll
            for (int h = 0; h < 2; h++) {
                int col = 8 * j + 2 * t + h;
                float e0 = 0.f, e1 = 0.f;
                if (col < CLS) {
                    e0 = __expf(c[j][h] - m0);
                    e1 = __expf(c[j][2 + h] - m1);
                }
                c[j][h] = e0; c[j][2 + h] = e1;
                s0 += e0; s1 += e1;
            }
        }
        #pragma unroll
        for (int d = 1; d <= 2; d <<= 1) {
            s0 += __shfl_xor_sync(0xffffffffu, s0, d);
            s1 += __shfl_xor_sync(0xffffffffu, s1, d);
        }
        const float v0inv = 1.0f / s0;
        const float v1inv = 1.0f / s1;
        #pragma unroll
        for (int j = 0; j < 10; j++) {
            int col = 8 * j + 2 * t;
            if (col < CLS) {   // excludes only (j=9,t=3) -> cols 78,79
                *(float2*)(out + (size_t)row0 * CLS + col) =
                    make_float2(c[j][0] * v0inv, c[j][1] * v0inv);
                *(float2*)(out + (size_t)row1 * CLS + col) =
                    make_float2(c[j][2] * v1inv, c[j][3] * v1inv);
            }
        }
        if (t == 0) { g_best[row0] = i0; g_best[row1] = i1; }
        __syncthreads();
    }
}

// ---------------------------------------------------------------------------
// CTC greedy decode: one warp per batch row, ballot compaction
// ---------------------------------------------------------------------------
__global__ void ctc_decode_kernel(float* __restrict__ out)
{
    const int gw = (blockIdx.x * blockDim.x + threadIdx.x) >> 5;
    const int lane = threadIdx.x & 31;
    const int wl = threadIdx.x >> 5;
    __shared__ float buf[8][32];
    if (gw >= BATCH) return;

    const int* bp = g_best + gw * TSTEPS;
    const unsigned full = 0xffffffffu;
    int v0 = bp[lane];
    int v1 = bp[lane + 32];
    int v2 = (lane < 16) ? bp[lane + 64] : BLANK;

    int p0 = __shfl_up_sync(full, v0, 1); if (lane == 0) p0 = -1;
    int t0 = __shfl_sync(full, v0, 31);
    int p1 = __shfl_up_sync(full, v1, 1); if (lane == 0) p1 = t0;
    int t1 = __shfl_sync(full, v1, 31);
    int p2 = __shfl_up_sync(full, v2, 1); if (lane == 0) p2 = t1;

    bool k0 = (v0 != BLANK) && (v0 != p0);
    bool k1 = (v1 != BLANK) && (v1 != p1);
    bool k2 = (lane < 16) && (v2 != BLANK) && (v2 != p2);
    unsigned m0 = __ballot_sync(full, k0);
    unsigned m1 = __ballot_sync(full, k1);
    unsigned m2 = __ballot_sync(full, k2);
    int c0 = __popc(m0), c1 = __popc(m1);
    unsigned lt = (1u << lane) - 1u;

    buf[wl][lane] = -1.0f;
    __syncwarp();
    if (k0) { int p = __popc(m0 & lt);           if (p < PRED_LEN) buf[wl][p] = (float)v0; }
    if (k1) { int p = c0 + __popc(m1 & lt);      if (p < PRED_LEN) buf[wl][p] = (float)v1; }
    if (k2) { int p = c0 + c1 + __popc(m2 & lt); if (p < PRED_LEN) buf[wl][p] = (float)v2; }
    __syncwarp();
    if (lane < PRED_LEN)
        out[(size_t)ROWS * CLS + (size_t)gw * PRED_LEN + lane] = buf[wl][lane];
}

// ---------------------------------------------------------------------------
extern "C" void kernel_launch(void* const* d_in, const int* in_sizes, int n_in,
                              void* d_out, int out_size)
{
    const float* feat = (const float*)d_in[0];
    const float* W    = (const float*)d_in[1];
    const float* b    = (const float*)d_in[2];
    float* out        = (float*)d_out;

    prep_w_kernel<<<(80 * 512 + 255) / 256, 256>>>(W);

    cudaFuncSetAttribute(gemm_softmax_kernel,
                         cudaFuncAttributeMaxDynamicSharedMemorySize, SM_TOTAL);
    gemm_softmax_kernel<<<NCTAS, THREADS, SM_TOTAL>>>(feat, b, out);

    ctc_decode_kernel<<<(BATCH * 32 + 255) / 256, 256>>>(out);
}